// round 4
// baseline (speedup 1.0000x reference)
#include <cuda_runtime.h>
#include <math.h>

#define TT 512
#define BB 64
#define VV 256
#define EE 512
#define HH 512

#define GRID_REC 128
#define NTH 256

#define W2   514      // float2 stride per weight column (padded)
#define SROW 516      // float stride per state row (padded)

// ---------------------------------------------------------------------------
// f32x2 packed helpers (FFMA2: 2 fp32 MACs per lane-op, bit-identical fp32)
// ---------------------------------------------------------------------------
typedef unsigned long long ull;
__device__ __forceinline__ ull pk2(float x, float y) {
    ull r; asm("mov.b64 %0,{%1,%2};" : "=l"(r) : "f"(x), "f"(y)); return r;
}
__device__ __forceinline__ ull pkd(float x) {
    ull r; asm("mov.b64 %0,{%1,%1};" : "=l"(r) : "f"(x)); return r;
}
__device__ __forceinline__ ull fma2(ull a, ull b, ull c) {
    ull d; asm("fma.rn.f32x2 %0,%1,%2,%3;" : "=l"(d) : "l"(a), "l"(b), "l"(c)); return d;
}
__device__ __forceinline__ ull add2(ull a, ull b) {
    ull d; asm("add.rn.f32x2 %0,%1,%2;" : "=l"(d) : "l"(a), "l"(b)); return d;
}
__device__ __forceinline__ float2 upk2(ull a) {
    float2 r; asm("mov.b64 {%0,%1},%2;" : "=f"(r.x), "=f"(r.y) : "l"(a)); return r;
}

// ---------------------------------------------------------------------------
// Static scratch
// ---------------------------------------------------------------------------
__device__ float g_table_t[2 * HH * VV];          // [j][v] : (emb @ w_in[0])^T
__device__ float g_stateA[BB * HH];               // state ping [b][k]
__device__ float g_stateB[BB * HH];               // state pong [b][k]
__device__ float g_out0[TT][HH * BB];             // layer-0 outputs [t][h][b]
__device__ float g_out1[TT][HH * BB];             // layer-1 outputs [t][h][b]
__device__ float g_in1[TT][2 * HH * BB];          // layer-1 input preact [t][j][b]
__device__ volatile unsigned g_flags[GRID_REC * 8];

__global__ void k_reset() {
    int idx = blockIdx.x * blockDim.x + threadIdx.x;
    if (idx < GRID_REC * 8) g_flags[idx] = 0u;
}

__global__ void k_noop() {}   // profile-slot alignment (ncu lands on 4th launch)

// ---------------------------------------------------------------------------
// g_table_t[j][v] = sum_e emb[v][e] * w_in[0][e][j]
// ---------------------------------------------------------------------------
__global__ void k_table(const float* __restrict__ emb,
                        const float* __restrict__ w_in) {
    int v = blockIdx.x;
    int j = threadIdx.x * 4;
    const float* er = emb + v * EE;
    float4 acc = make_float4(0.f, 0.f, 0.f, 0.f);
#pragma unroll 4
    for (int e = 0; e < EE; ++e) {
        float ev = er[e];
        float4 wv = *reinterpret_cast<const float4*>(w_in + (size_t)e * (2 * HH) + j);
        acc.x = fmaf(ev, wv.x, acc.x);
        acc.y = fmaf(ev, wv.y, acc.y);
        acc.z = fmaf(ev, wv.z, acc.z);
        acc.w = fmaf(ev, wv.w, acc.w);
    }
    g_table_t[(j + 0) * VV + v] = acc.x;
    g_table_t[(j + 1) * VV + v] = acc.y;
    g_table_t[(j + 2) * VV + v] = acc.z;
    g_table_t[(j + 3) * VV + v] = acc.w;
}

// ---------------------------------------------------------------------------
// All-poll grid barrier: each CTA publishes its flag; threads 0..127 of every
// CTA poll all 128 flags directly (one L2 round trip, no master hop).
// ---------------------------------------------------------------------------
__device__ __forceinline__ void gbar(int cid, int tid, unsigned epoch) {
    __threadfence();                // release: order this thread's state STGs
    __syncthreads();                // all threads of CTA fenced + arrived
    if (tid == 0) g_flags[cid * 8] = epoch;
    if (tid < GRID_REC) {
        while (g_flags[tid * 8] < epoch) { }
    }
    __syncthreads();
}

// ---------------------------------------------------------------------------
// Persistent RHN pass. PASS=0: layer 0 (input via table gather).
//                      PASS=1: layer 1 (input preact from g_in1).
// 128 CTAs = 2 row-groups x 64 col-groups. CTA tile: 32 rows x 8 colpairs.
// Warp = 4 rows x 8 colpairs (lane = rr*8+c). Thread computes one (row,colpair)
// with a packed f32x2 accumulator (h,g).
// State [b][k] staged per step into padded SMEM; conflict-free float4 LDS
// (4 k / load, 64B/wavefront after dedup). Weights padded (h,g) float2,
// conflict-free ulonglong2 LDS (2 k / load).
// ---------------------------------------------------------------------------
template <int PASS>
__global__ void __launch_bounds__(NTH, 1) k_rhn(
    const int*   __restrict__ x,
    const float* __restrict__ w_h,
    const float* __restrict__ b_h,
    unsigned ebase)
{
    extern __shared__ float smraw[];
    float2* w_sh2 = reinterpret_cast<float2*>(smraw);       // [4][8][W2] float2 (131.6 KB)
    float*  s_sh  = smraw + 2 * (4 * 8 * W2);               // [32][SROW]        (66.0 KB)

    const int tid  = threadIdx.x;
    const int cid  = blockIdx.x;
    const int rg   = cid & 1;
    const int cg   = cid >> 1;
    const int w    = tid >> 5;
    const int lane = tid & 31;
    const int rr   = lane >> 3;
    const int c    = lane & 7;
    const int lrow = 4 * w + rr;           // local row 0..31
    const int grow = rg * 32 + lrow;       // global batch row
    const int scol = cg * 8 + c;           // colpair 0..511

    // ---- stage weights for all 4 depth steps, (h,g) interleaved, padded ----
    for (int idx = tid; idx < 4 * 8 * HH; idx += NTH) {
        int c2 = idx & 7;
        int k  = (idx >> 3) & (HH - 1);
        int d  = idx >> 12;
        const float* wb = w_h + (((size_t)(PASS * 4 + d) * HH + k) * (2 * HH)) + cg * 8 + c2;
        w_sh2[(d * 8 + c2) * W2 + k] = make_float2(wb[0], wb[HH]);
    }

    // ---- packed biases ----
    ull bias_pk[4];
#pragma unroll
    for (int d = 0; d < 4; ++d) {
        bias_pk[d] = pk2(b_h[(size_t)(PASS * 4 + d) * (2 * HH) + scol],
                         b_h[(size_t)(PASS * 4 + d) * (2 * HH) + HH + scol]);
    }
    __syncthreads();

    const float* s_cur = g_stateA;
    float*       s_nxt = g_stateB;
    unsigned epoch = ebase;

    const float4*     sp4 = reinterpret_cast<const float4*>(s_sh + lrow * SROW);
    const ulonglong2* wpB = reinterpret_cast<const ulonglong2*>(w_sh2);

    for (int t = 0; t < TT; ++t) {
        // d0 input (packed), fetched early
        ull inp0;
        if (PASS == 0) {
            int xv = x[t * BB + grow];
            inp0 = pk2(g_table_t[(size_t)scol * VV + xv],
                       g_table_t[(size_t)(HH + scol) * VV + xv]);
        } else {
            inp0 = pk2(g_in1[t][scol * BB + grow],
                       g_in1[t][(HH + scol) * BB + grow]);
        }

        for (int d = 0; d < 4; ++d) {
            // ---- stage state tile [32][512] -> padded s_sh ----
            if (t == 0 && d == 0) {
#pragma unroll
                for (int i = tid; i < 4096; i += NTH) {
                    int b = i >> 7, q = i & 127;
                    *reinterpret_cast<float4*>(s_sh + b * SROW + 4 * q) =
                        make_float4(0.f, 0.f, 0.f, 0.f);
                }
            } else {
#pragma unroll
                for (int i = tid; i < 4096; i += NTH) {
                    int b = i >> 7, q = i & 127;
                    *reinterpret_cast<float4*>(s_sh + b * SROW + 4 * q) =
                        __ldcg(reinterpret_cast<const float4*>(
                            s_cur + (size_t)(rg * 32 + b) * HH + 4 * q));
                }
            }
            __syncthreads();

            // ---- packed K-dot: acc(h,g) = bias (+input) + sum_k s_k * (wh,wg)_k
            ull acc0 = bias_pk[d];
            if (d == 0) acc0 = add2(acc0, inp0);
            ull acc1 = pk2(0.f, 0.f);

            const ulonglong2* wp = wpB + (size_t)(d * 8 + c) * (W2 / 2);
#pragma unroll 8
            for (int q = 0; q < 128; ++q) {
                float4 s4 = sp4[q];
                ulonglong2 wA = wp[2 * q];
                ulonglong2 wB = wp[2 * q + 1];
                acc0 = fma2(pkd(s4.x), wA.x, acc0);
                acc1 = fma2(pkd(s4.y), wA.y, acc1);
                acc0 = fma2(pkd(s4.z), wB.x, acc0);
                acc1 = fma2(pkd(s4.w), wB.y, acc1);
            }
            float2 a = upk2(add2(acc0, acc1));

            float s_old = s_sh[lrow * SROW + scol];
            float gt = 1.0f / (1.0f + expf(-a.y));
            float ht = tanhf(a.x);
            float s_new = ht * gt + s_old * (1.0f - gt);

            s_nxt[(size_t)grow * HH + scol] = s_new;
            if (d == 3) {
                float* ob = (PASS == 0) ? g_out0[t] : g_out1[t];
                ob[scol * BB + grow] = s_new;       // [h][b] copy for epilogues
            }

            ++epoch;
            gbar(cid, tid, epoch);

            const float* tmp = s_nxt;
            s_nxt = (float*)s_cur;
            s_cur = tmp;
        }
    }
}

// ---------------------------------------------------------------------------
// g_in1[t][j][b] = sum_h g_out0[t][h][b] * w_in[1][h][j]   (FFMA2)
// ---------------------------------------------------------------------------
__global__ void k_inp1(const float* __restrict__ w_in) {
    int bid = blockIdx.x;
    int t   = bid >> 4;
    int jb  = bid & 15;
    int tid = threadIdx.x;
    int b   = tid & 63;
    int js  = tid >> 6;
    int j0  = jb * 64 + js * 16;

    ull acc[8];
#pragma unroll
    for (int i = 0; i < 8; ++i) acc[i] = pk2(0.f, 0.f);

    const float* o  = g_out0[t];
    const float* w1 = w_in + (size_t)EE * (2 * HH);
#pragma unroll 2
    for (int h = 0; h < HH; ++h) {
        ull svp = pkd(o[h * BB + b]);
        const ulonglong2* wr = reinterpret_cast<const ulonglong2*>(w1 + (size_t)h * (2 * HH) + j0);
        ulonglong2 q0 = wr[0], q1 = wr[1], q2 = wr[2], q3 = wr[3];
        acc[0] = fma2(svp, q0.x, acc[0]);  acc[1] = fma2(svp, q0.y, acc[1]);
        acc[2] = fma2(svp, q1.x, acc[2]);  acc[3] = fma2(svp, q1.y, acc[3]);
        acc[4] = fma2(svp, q2.x, acc[4]);  acc[5] = fma2(svp, q2.y, acc[5]);
        acc[6] = fma2(svp, q3.x, acc[6]);  acc[7] = fma2(svp, q3.y, acc[7]);
    }
#pragma unroll
    for (int i = 0; i < 8; ++i) {
        float2 v = upk2(acc[i]);
        g_in1[t][(j0 + 2 * i) * BB + b]     = v.x;
        g_in1[t][(j0 + 2 * i + 1) * BB + b] = v.y;
    }
}

// ---------------------------------------------------------------------------
// logits[t][b][v] = sum_h g_out1[t][h][b] * w_fc[h][v] + b_fc[v]   (FFMA2)
// ---------------------------------------------------------------------------
__global__ void k_logits(const float* __restrict__ w_fc,
                         const float* __restrict__ b_fc,
                         float* __restrict__ out) {
    int bid = blockIdx.x;
    int t   = bid >> 2;
    int vb  = bid & 3;
    int tid = threadIdx.x;
    int b   = tid & 63;
    int vs  = tid >> 6;
    int v0  = vb * 64 + vs * 16;

    ull acc[8];
    const ulonglong2* bp = reinterpret_cast<const ulonglong2*>(b_fc + v0);
#pragma unroll
    for (int i = 0; i < 4; ++i) {
        ulonglong2 bq = bp[i];
        acc[2 * i] = bq.x; acc[2 * i + 1] = bq.y;
    }

    const float* o = g_out1[t];
#pragma unroll 2
    for (int h = 0; h < HH; ++h) {
        ull svp = pkd(o[h * BB + b]);
        const ulonglong2* wr = reinterpret_cast<const ulonglong2*>(w_fc + (size_t)h * VV + v0);
        ulonglong2 q0 = wr[0], q1 = wr[1], q2 = wr[2], q3 = wr[3];
        acc[0] = fma2(svp, q0.x, acc[0]);  acc[1] = fma2(svp, q0.y, acc[1]);
        acc[2] = fma2(svp, q1.x, acc[2]);  acc[3] = fma2(svp, q1.y, acc[3]);
        acc[4] = fma2(svp, q2.x, acc[4]);  acc[5] = fma2(svp, q2.y, acc[5]);
        acc[6] = fma2(svp, q3.x, acc[6]);  acc[7] = fma2(svp, q3.y, acc[7]);
    }

    ull* dst = reinterpret_cast<ull*>(out + ((size_t)(t * BB + b)) * VV + v0);
#pragma unroll
    for (int i = 0; i < 8; ++i) dst[i] = acc[i];
}

// ---------------------------------------------------------------------------
// s_final[l][b][h]: final state lives in g_stateA ([b][h]) after each pass.
// ---------------------------------------------------------------------------
__global__ void k_sfinal(float* __restrict__ out, int l) {
    int idx = blockIdx.x * blockDim.x + threadIdx.x;
    if (idx >= BB * HH) return;
    out[(size_t)TT * BB * VV + (size_t)l * BB * HH + idx] = g_stateA[idx];
}

// ---------------------------------------------------------------------------
extern "C" void kernel_launch(void* const* d_in, const int* in_sizes, int n_in,
                              void* d_out, int out_size) {
    const int*   x    = (const int*)  d_in[0];
    const float* emb  = (const float*)d_in[1];
    const float* w_in = (const float*)d_in[2];
    const float* w_h  = (const float*)d_in[3];
    const float* b_h  = (const float*)d_in[4];
    const float* w_fc = (const float*)d_in[5];
    const float* b_fc = (const float*)d_in[6];
    float* out = (float*)d_out;

    const int smem_bytes = (2 * 4 * 8 * W2 + 32 * SROW) * (int)sizeof(float); // 197632 B
    static bool attr_done = false;
    if (!attr_done) {
        cudaFuncSetAttribute(k_rhn<0>, cudaFuncAttributeMaxDynamicSharedMemorySize, smem_bytes);
        cudaFuncSetAttribute(k_rhn<1>, cudaFuncAttributeMaxDynamicSharedMemorySize, smem_bytes);
        attr_done = true;
    }

    const bool has_sfinal = (out_size >= TT * BB * VV + 2 * BB * HH);

    k_reset<<<1, NTH>>>();                                              // 1
    k_table<<<VV, NTH>>>(emb, w_in);                                    // 2
    k_noop<<<1, 32>>>();                                                // 3 (slot pad)
    k_rhn<0><<<GRID_REC, NTH, smem_bytes>>>(x, w_h, b_h, 0u);           // 4 <- profiled
    if (has_sfinal)
        k_sfinal<<<(BB * HH + NTH - 1) / NTH, NTH>>>(out, 0);
    k_inp1<<<TT * 16, NTH>>>(w_in);
    k_rhn<1><<<GRID_REC, NTH, smem_bytes>>>(x, w_h, b_h, 2048u);
    k_logits<<<TT * 4, NTH>>>(w_fc, b_fc, out);
    if (has_sfinal)
        k_sfinal<<<(BB * HH + NTH - 1) / NTH, NTH>>>(out, 1);
}

// round 5
// speedup vs baseline: 1.0768x; 1.0768x over previous
#include <cuda_runtime.h>
#include <math.h>

#define TT 512
#define BB 64
#define VV 256
#define EE 512
#define HH 512

#define GRID_REC 128
#define NTH 256

#define W2   514      // float2 stride per weight column (padded)
#define SROW 516      // float stride per state row (padded)

// ---------------------------------------------------------------------------
// f32x2 packed helpers (FFMA2: 2 fp32 MACs per lane-op, bit-identical fp32)
// ---------------------------------------------------------------------------
typedef unsigned long long ull;
__device__ __forceinline__ ull pk2(float x, float y) {
    ull r; asm("mov.b64 %0,{%1,%2};" : "=l"(r) : "f"(x), "f"(y)); return r;
}
__device__ __forceinline__ ull pkd(float x) {
    ull r; asm("mov.b64 %0,{%1,%1};" : "=l"(r) : "f"(x)); return r;
}
__device__ __forceinline__ ull fma2(ull a, ull b, ull c) {
    ull d; asm("fma.rn.f32x2 %0,%1,%2,%3;" : "=l"(d) : "l"(a), "l"(b), "l"(c)); return d;
}
__device__ __forceinline__ ull add2(ull a, ull b) {
    ull d; asm("add.rn.f32x2 %0,%1,%2;" : "=l"(d) : "l"(a), "l"(b)); return d;
}
__device__ __forceinline__ float2 upk2(ull a) {
    float2 r; asm("mov.b64 {%0,%1},%2;" : "=f"(r.x), "=f"(r.y) : "l"(a)); return r;
}

// ---------------------------------------------------------------------------
// Static scratch
// ---------------------------------------------------------------------------
__device__ float g_table_t[2 * HH * VV];          // [j][v] : (emb @ w_in[0])^T
__device__ float g_stateA[BB * HH];               // state ping [b][k]
__device__ float g_stateB[BB * HH];               // state pong [b][k]
__device__ float g_out0[TT][HH * BB];             // layer-0 outputs [t][h][b]
__device__ float g_out1[TT][HH * BB];             // layer-1 outputs [t][h][b]
__device__ float g_in1[TT][2 * HH * BB];          // layer-1 input preact [t][j][b]
__device__ volatile unsigned g_flags[GRID_REC * 32];   // 128B line per CTA
__device__ volatile unsigned g_phaseArr[2 * 32];       // release word per row group

__global__ void k_reset() {
    int idx = blockIdx.x * blockDim.x + threadIdx.x;
    if (idx < GRID_REC * 32) g_flags[idx] = 0u;
    if (idx < 2 * 32) g_phaseArr[idx] = 0u;
}

__global__ void k_noop() {}   // profile-slot alignment (ncu lands on 4th launch)

// ---------------------------------------------------------------------------
// g_table_t[j][v] = sum_e emb[v][e] * w_in[0][e][j]
// ---------------------------------------------------------------------------
__global__ void k_table(const float* __restrict__ emb,
                        const float* __restrict__ w_in) {
    int v = blockIdx.x;
    int j = threadIdx.x * 4;
    const float* er = emb + v * EE;
    float4 acc = make_float4(0.f, 0.f, 0.f, 0.f);
#pragma unroll 4
    for (int e = 0; e < EE; ++e) {
        float ev = er[e];
        float4 wv = *reinterpret_cast<const float4*>(w_in + (size_t)e * (2 * HH) + j);
        acc.x = fmaf(ev, wv.x, acc.x);
        acc.y = fmaf(ev, wv.y, acc.y);
        acc.z = fmaf(ev, wv.z, acc.z);
        acc.w = fmaf(ev, wv.w, acc.w);
    }
    g_table_t[(j + 0) * VV + v] = acc.x;
    g_table_t[(j + 1) * VV + v] = acc.y;
    g_table_t[(j + 2) * VV + v] = acc.z;
    g_table_t[(j + 3) * VV + v] = acc.w;
}

// ---------------------------------------------------------------------------
// Group barrier over the 64 CTAs of one row group (cid ≡ rg mod 2).
// Master (cid==rg): threads 1..63 gather member flags, thread0 releases phase.
// Members: thread 0 publishes flag, polls the single release word.
// ---------------------------------------------------------------------------
__device__ __forceinline__ void gbar(int rg, int cid, int tid, unsigned epoch) {
    __threadfence();           // release: order this thread's state STGs
    __syncthreads();           // whole CTA arrived + fenced
    if (cid == rg) {           // master CTA of this row group
        if (tid >= 1 && tid < 64) {
            while (g_flags[(rg + 2 * tid) * 32] < epoch) { }
        }
        __syncthreads();
        if (tid == 0) {
            __threadfence();   // chain acquire->release for cumulativity
            g_phaseArr[rg * 32] = epoch;
        }
    } else {
        if (tid == 0) {
            g_flags[cid * 32] = epoch;
            while (g_phaseArr[rg * 32] < epoch) { }
        }
    }
    __syncthreads();
}

// ---------------------------------------------------------------------------
// Persistent RHN pass. PASS=0: layer 0 (input via table gather).
//                      PASS=1: layer 1 (input preact from g_in1).
// 128 CTAs = 2 independent row-group domains x 64 col groups.
// CTA tile: 32 rows x 8 colpairs. Warp = 4 rows x 8 colpairs.
// Thread: one (row,colpair), packed f32x2 (h,g) accumulator, 4 chains.
// ---------------------------------------------------------------------------
template <int PASS>
__global__ void __launch_bounds__(NTH, 1) k_rhn(
    const int*   __restrict__ x,
    const float* __restrict__ w_h,
    const float* __restrict__ b_h,
    unsigned ebase)
{
    extern __shared__ float smraw[];
    float2* w_sh2 = reinterpret_cast<float2*>(smraw);       // [4][8][W2] float2
    float*  s_sh  = smraw + 2 * (4 * 8 * W2);               // [32][SROW]

    const int tid  = threadIdx.x;
    const int cid  = blockIdx.x;
    const int rg   = cid & 1;
    const int cg   = cid >> 1;
    const int w    = tid >> 5;
    const int lane = tid & 31;
    const int rr   = lane >> 3;
    const int c    = lane & 7;
    const int lrow = 4 * w + rr;
    const int grow = rg * 32 + lrow;
    const int scol = cg * 8 + c;

    // ---- stage weights for all 4 depth steps, (h,g) interleaved, padded ----
    for (int idx = tid; idx < 4 * 8 * HH; idx += NTH) {
        int c2 = idx & 7;
        int k  = (idx >> 3) & (HH - 1);
        int d  = idx >> 12;
        const float* wb = w_h + (((size_t)(PASS * 4 + d) * HH + k) * (2 * HH)) + cg * 8 + c2;
        w_sh2[(d * 8 + c2) * W2 + k] = make_float2(wb[0], wb[HH]);
    }

    ull bias_pk[4];
#pragma unroll
    for (int d = 0; d < 4; ++d) {
        bias_pk[d] = pk2(b_h[(size_t)(PASS * 4 + d) * (2 * HH) + scol],
                         b_h[(size_t)(PASS * 4 + d) * (2 * HH) + HH + scol]);
    }
    __syncthreads();

    const float* s_cur = g_stateA;
    float*       s_nxt = g_stateB;
    unsigned epoch = ebase;

    const float4*     sp4 = reinterpret_cast<const float4*>(s_sh + lrow * SROW);
    const ulonglong2* wpB = reinterpret_cast<const ulonglong2*>(w_sh2);

    // prefetch t=0 input
    ull inp_cur;
    if (PASS == 0) {
        int xv = x[0 * BB + grow];
        inp_cur = pk2(g_table_t[(size_t)scol * VV + xv],
                      g_table_t[(size_t)(HH + scol) * VV + xv]);
    } else {
        inp_cur = pk2(__ldcg(&g_in1[0][scol * BB + grow]),
                      __ldcg(&g_in1[0][(HH + scol) * BB + grow]));
    }

    for (int t = 0; t < TT; ++t) {
        ull inp_next = 0;
        for (int d = 0; d < 4; ++d) {
            // ---- stage state tile [32][512] -> padded s_sh ----
            if (t == 0 && d == 0) {
#pragma unroll
                for (int i = tid; i < 4096; i += NTH) {
                    int b = i >> 7, q = i & 127;
                    *reinterpret_cast<float4*>(s_sh + b * SROW + 4 * q) =
                        make_float4(0.f, 0.f, 0.f, 0.f);
                }
            } else {
#pragma unroll
                for (int i = tid; i < 4096; i += NTH) {
                    int b = i >> 7, q = i & 127;
                    *reinterpret_cast<float4*>(s_sh + b * SROW + 4 * q) =
                        __ldcg(reinterpret_cast<const float4*>(
                            s_cur + (size_t)(rg * 32 + b) * HH + 4 * q));
                }
            }
            __syncthreads();

            // prefetch input for t+1 while this step computes (hide latency)
            if (d == 0 && t + 1 < TT) {
                if (PASS == 0) {
                    int xv = x[(t + 1) * BB + grow];
                    inp_next = pk2(g_table_t[(size_t)scol * VV + xv],
                                   g_table_t[(size_t)(HH + scol) * VV + xv]);
                } else {
                    inp_next = pk2(__ldcg(&g_in1[t + 1][scol * BB + grow]),
                                   __ldcg(&g_in1[t + 1][(HH + scol) * BB + grow]));
                }
            }

            // ---- packed K-dot: acc(h,g) = bias (+input at d0) + s @ W_d ----
            ull acc0 = bias_pk[d];
            if (d == 0) acc0 = add2(acc0, inp_cur);
            ull acc1 = pk2(0.f, 0.f);
            ull acc2 = pk2(0.f, 0.f);
            ull acc3 = pk2(0.f, 0.f);

            const ulonglong2* wp = wpB + (size_t)(d * 8 + c) * (W2 / 2);
#pragma unroll 8
            for (int q = 0; q < 128; ++q) {
                float4 s4 = sp4[q];
                ulonglong2 wA = wp[2 * q];
                ulonglong2 wB = wp[2 * q + 1];
                acc0 = fma2(pkd(s4.x), wA.x, acc0);
                acc1 = fma2(pkd(s4.y), wA.y, acc1);
                acc2 = fma2(pkd(s4.z), wB.x, acc2);
                acc3 = fma2(pkd(s4.w), wB.y, acc3);
            }
            float2 a = upk2(add2(add2(acc0, acc1), add2(acc2, acc3)));

            float s_old = s_sh[lrow * SROW + scol];
            float gt = 1.0f / (1.0f + expf(-a.y));
            float ht = tanhf(a.x);
            float s_new = ht * gt + s_old * (1.0f - gt);

            s_nxt[(size_t)grow * HH + scol] = s_new;
            if (d == 3) {
                float* ob = (PASS == 0) ? g_out0[t] : g_out1[t];
                ob[scol * BB + grow] = s_new;       // [h][b] for epilogues
            }

            ++epoch;
            gbar(rg, cid, tid, epoch);

            const float* tmp = s_nxt;
            s_nxt = (float*)s_cur;
            s_cur = tmp;
        }
        inp_cur = inp_next;
    }
}

// ---------------------------------------------------------------------------
// g_in1[t][j][b] = sum_h g_out0[t][h][b] * w_in[1][h][j]   (FFMA2)
// ---------------------------------------------------------------------------
__global__ void k_inp1(const float* __restrict__ w_in) {
    int bid = blockIdx.x;
    int t   = bid >> 4;
    int jb  = bid & 15;
    int tid = threadIdx.x;
    int b   = tid & 63;
    int js  = tid >> 6;
    int j0  = jb * 64 + js * 16;

    ull acc[8];
#pragma unroll
    for (int i = 0; i < 8; ++i) acc[i] = pk2(0.f, 0.f);

    const float* o  = g_out0[t];
    const float* w1 = w_in + (size_t)EE * (2 * HH);
#pragma unroll 2
    for (int h = 0; h < HH; ++h) {
        ull svp = pkd(o[h * BB + b]);
        const ulonglong2* wr = reinterpret_cast<const ulonglong2*>(w1 + (size_t)h * (2 * HH) + j0);
        ulonglong2 q0 = wr[0], q1 = wr[1], q2 = wr[2], q3 = wr[3];
        acc[0] = fma2(svp, q0.x, acc[0]);  acc[1] = fma2(svp, q0.y, acc[1]);
        acc[2] = fma2(svp, q1.x, acc[2]);  acc[3] = fma2(svp, q1.y, acc[3]);
        acc[4] = fma2(svp, q2.x, acc[4]);  acc[5] = fma2(svp, q2.y, acc[5]);
        acc[6] = fma2(svp, q3.x, acc[6]);  acc[7] = fma2(svp, q3.y, acc[7]);
    }
#pragma unroll
    for (int i = 0; i < 8; ++i) {
        float2 v = upk2(acc[i]);
        g_in1[t][(j0 + 2 * i) * BB + b]     = v.x;
        g_in1[t][(j0 + 2 * i + 1) * BB + b] = v.y;
    }
}

// ---------------------------------------------------------------------------
// logits[t][b][v] = sum_h g_out1[t][h][b] * w_fc[h][v] + b_fc[v]   (FFMA2)
// ---------------------------------------------------------------------------
__global__ void k_logits(const float* __restrict__ w_fc,
                         const float* __restrict__ b_fc,
                         float* __restrict__ out) {
    int bid = blockIdx.x;
    int t   = bid >> 2;
    int vb  = bid & 3;
    int tid = threadIdx.x;
    int b   = tid & 63;
    int vs  = tid >> 6;
    int v0  = vb * 64 + vs * 16;

    ull acc[8];
    const ulonglong2* bp = reinterpret_cast<const ulonglong2*>(b_fc + v0);
#pragma unroll
    for (int i = 0; i < 4; ++i) {
        ulonglong2 bq = bp[i];
        acc[2 * i] = bq.x; acc[2 * i + 1] = bq.y;
    }

    const float* o = g_out1[t];
#pragma unroll 2
    for (int h = 0; h < HH; ++h) {
        ull svp = pkd(o[h * BB + b]);
        const ulonglong2* wr = reinterpret_cast<const ulonglong2*>(w_fc + (size_t)h * VV + v0);
        ulonglong2 q0 = wr[0], q1 = wr[1], q2 = wr[2], q3 = wr[3];
        acc[0] = fma2(svp, q0.x, acc[0]);  acc[1] = fma2(svp, q0.y, acc[1]);
        acc[2] = fma2(svp, q1.x, acc[2]);  acc[3] = fma2(svp, q1.y, acc[3]);
        acc[4] = fma2(svp, q2.x, acc[4]);  acc[5] = fma2(svp, q2.y, acc[5]);
        acc[6] = fma2(svp, q3.x, acc[6]);  acc[7] = fma2(svp, q3.y, acc[7]);
    }

    ull* dst = reinterpret_cast<ull*>(out + ((size_t)(t * BB + b)) * VV + v0);
#pragma unroll
    for (int i = 0; i < 8; ++i) dst[i] = acc[i];
}

// ---------------------------------------------------------------------------
// s_final[l][b][h]: final state lives in g_stateA ([b][h]) after each pass.
// ---------------------------------------------------------------------------
__global__ void k_sfinal(float* __restrict__ out, int l) {
    int idx = blockIdx.x * blockDim.x + threadIdx.x;
    if (idx >= BB * HH) return;
    out[(size_t)TT * BB * VV + (size_t)l * BB * HH + idx] = g_stateA[idx];
}

// ---------------------------------------------------------------------------
extern "C" void kernel_launch(void* const* d_in, const int* in_sizes, int n_in,
                              void* d_out, int out_size) {
    const int*   x    = (const int*)  d_in[0];
    const float* emb  = (const float*)d_in[1];
    const float* w_in = (const float*)d_in[2];
    const float* w_h  = (const float*)d_in[3];
    const float* b_h  = (const float*)d_in[4];
    const float* w_fc = (const float*)d_in[5];
    const float* b_fc = (const float*)d_in[6];
    float* out = (float*)d_out;

    const int smem_bytes = (2 * 4 * 8 * W2 + 32 * SROW) * (int)sizeof(float); // 197632 B
    static bool attr_done = false;
    if (!attr_done) {
        cudaFuncSetAttribute(k_rhn<0>, cudaFuncAttributeMaxDynamicSharedMemorySize, smem_bytes);
        cudaFuncSetAttribute(k_rhn<1>, cudaFuncAttributeMaxDynamicSharedMemorySize, smem_bytes);
        attr_done = true;
    }

    const bool has_sfinal = (out_size >= TT * BB * VV + 2 * BB * HH);

    k_reset<<<(GRID_REC * 32 + NTH - 1) / NTH, NTH>>>();                // 1
    k_table<<<VV, NTH>>>(emb, w_in);                                    // 2
    k_noop<<<1, 32>>>();                                                // 3 (slot pad)
    k_rhn<0><<<GRID_REC, NTH, smem_bytes>>>(x, w_h, b_h, 0u);           // 4 <- profiled
    if (has_sfinal)
        k_sfinal<<<(BB * HH + NTH - 1) / NTH, NTH>>>(out, 0);
    k_inp1<<<TT * 16, NTH>>>(w_in);
    k_rhn<1><<<GRID_REC, NTH, smem_bytes>>>(x, w_h, b_h, 2048u);
    k_logits<<<TT * 4, NTH>>>(w_fc, b_fc, out);
    if (has_sfinal)
        k_sfinal<<<(BB * HH + NTH - 1) / NTH, NTH>>>(out, 1);
}

// round 6
// speedup vs baseline: 1.0812x; 1.0041x over previous
#include <cuda_runtime.h>
#include <math.h>

#define TT 512
#define BB 64
#define VV 256
#define EE 512
#define HH 512

#define GRID_REC 128
#define NTH 512

#define SROWF 520          // float stride per state row (pad: 16B-aligned, bank-skewed)
#define WCOL  257          // ull2 stride per (d,col) weight column (pad)

typedef unsigned long long ull;
__device__ __forceinline__ ull pk2(float x, float y) {
    ull r; asm("mov.b64 %0,{%1,%2};" : "=l"(r) : "f"(x), "f"(y)); return r;
}
__device__ __forceinline__ ull pkd(float x) {
    ull r; asm("mov.b64 %0,{%1,%1};" : "=l"(r) : "f"(x)); return r;
}
__device__ __forceinline__ ull fma2(ull a, ull b, ull c) {
    ull d; asm("fma.rn.f32x2 %0,%1,%2,%3;" : "=l"(d) : "l"(a), "l"(b), "l"(c)); return d;
}
__device__ __forceinline__ ull add2(ull a, ull b) {
    ull d; asm("add.rn.f32x2 %0,%1,%2;" : "=l"(d) : "l"(a), "l"(b)); return d;
}
__device__ __forceinline__ float2 upk2(ull a) {
    float2 r; asm("mov.b64 {%0,%1},%2;" : "=f"(r.x), "=f"(r.y) : "l"(a)); return r;
}

// ---------------------------------------------------------------------------
__device__ float g_table_t[2 * HH * VV];          // [j][v] : (emb @ w_in[0])^T
__device__ float g_stateA[BB * HH];               // state ping [b][k]
__device__ float g_stateB[BB * HH];               // state pong [b][k]
__device__ float g_out0[TT][HH * BB];             // layer-0 outputs [t][h][b]
__device__ float g_out1[TT][HH * BB];             // layer-1 outputs [t][h][b]
__device__ float g_in1[TT][2 * HH * BB];          // layer-1 input preact [t][j][b]
__device__ volatile unsigned g_flags[GRID_REC * 32];
__device__ volatile unsigned g_phaseArr[2 * 32];

__global__ void k_reset() {
    int idx = blockIdx.x * blockDim.x + threadIdx.x;
    if (idx < GRID_REC * 32) g_flags[idx] = 0u;
    if (idx < 2 * 32) g_phaseArr[idx] = 0u;
}

__global__ void k_noop() {}   // profile-slot pad (ncu lands on 4th launch)

// ---------------------------------------------------------------------------
__global__ void k_table(const float* __restrict__ emb,
                        const float* __restrict__ w_in) {
    int v = blockIdx.x;
    int j = threadIdx.x * 4;
    const float* er = emb + v * EE;
    float4 acc = make_float4(0.f, 0.f, 0.f, 0.f);
#pragma unroll 4
    for (int e = 0; e < EE; ++e) {
        float ev = er[e];
        float4 wv = *reinterpret_cast<const float4*>(w_in + (size_t)e * (2 * HH) + j);
        acc.x = fmaf(ev, wv.x, acc.x);
        acc.y = fmaf(ev, wv.y, acc.y);
        acc.z = fmaf(ev, wv.z, acc.z);
        acc.w = fmaf(ev, wv.w, acc.w);
    }
    g_table_t[(j + 0) * VV + v] = acc.x;
    g_table_t[(j + 1) * VV + v] = acc.y;
    g_table_t[(j + 2) * VV + v] = acc.z;
    g_table_t[(j + 3) * VV + v] = acc.w;
}

// ---------------------------------------------------------------------------
// 64-CTA row-group barrier, master-gather (master = CTA rg).
// ---------------------------------------------------------------------------
__device__ __forceinline__ void gbar(int rg, int cid, int tid, unsigned epoch) {
    __threadfence();
    __syncthreads();
    if (cid == rg) {
        if (tid >= 1 && tid < 64) {
            while (g_flags[(rg + 2 * tid) * 32] < epoch) { }
        }
        __syncthreads();
        if (tid == 0) {
            __threadfence();
            g_phaseArr[rg * 32] = epoch;
        }
    } else {
        if (tid == 0) {
            g_flags[cid * 32] = epoch;
            while (g_phaseArr[rg * 32] < epoch) { }
        }
    }
    __syncthreads();
}

// ---------------------------------------------------------------------------
// Persistent RHN pass. 128 CTAs = 2 rowgroup domains x 64 colgroups.
// CTA tile: 32 rows x 8 cols. 512 threads: warp = 4 rows x 8 cols,
// warps 0..7 = k[0,256), warps 8..15 = k[256,512) (split-k + smem reduce).
// k-pair packed FFMA2: state LDS.128 = 4 packed k's, weights ull2 (wh,wh)(wg,wg).
// ---------------------------------------------------------------------------
template <int PASS>
__global__ void __launch_bounds__(NTH, 1) k_rhn(
    const int*   __restrict__ x,
    const float* __restrict__ w_h,
    const float* __restrict__ b_h,
    unsigned ebase)
{
    extern __shared__ float smraw[];
    ulonglong2* w_pk    = reinterpret_cast<ulonglong2*>(smraw);        // [4][8][WCOL] (131584 B)
    float*      s_sh    = smraw + 32896;                               // [32][SROWF]  (66560 B)
    float2*     scratch = reinterpret_cast<float2*>(s_sh + 32 * SROWF); // [32][8]     (2048 B)

    const int tid   = threadIdx.x;
    const int cid   = blockIdx.x;
    const int rg    = cid & 1;
    const int cg    = cid >> 1;
    const int w     = tid >> 5;
    const int lane  = tid & 31;
    const int rr    = lane >> 3;
    const int c     = lane & 7;
    const int wq    = w & 7;            // row-quad
    const int khalf = w >> 3;           // 0 / 1
    const int lrow  = wq * 4 + rr;      // local row 0..31
    const int grow  = rg * 32 + lrow;   // global batch row
    const int scol  = cg * 8 + c;       // H-index 0..511

    // ---- stage weights: w_pk[(d*8+cp)*WCOL + kp] = {(wh_k0,wh_k1),(wg_k0,wg_k1)}
    // idx = (d*256 + kp)*8 + cp  (cp fastest -> coalesced-ish global reads)
    for (int idx = tid; idx < 4 * 256 * 8; idx += NTH) {
        int cp = idx & 7;
        int kp = (idx >> 3) & 255;
        int d  = idx >> 11;
        const float* b0 = w_h + (((size_t)(PASS * 4 + d) * HH + 2 * kp) * (2 * HH)) + cg * 8 + cp;
        const float* b1 = b0 + 2 * HH;
        w_pk[(d * 8 + cp) * WCOL + kp] =
            make_ulonglong2(pk2(b0[0], b1[0]), pk2(b0[HH], b1[HH]));
    }

    float bh[4], bg[4];
#pragma unroll
    for (int d = 0; d < 4; ++d) {
        bh[d] = b_h[(size_t)(PASS * 4 + d) * (2 * HH) + scol];
        bg[d] = b_h[(size_t)(PASS * 4 + d) * (2 * HH) + HH + scol];
    }
    __syncthreads();

    const float* s_cur = g_stateA;
    float*       s_nxt = g_stateB;
    unsigned epoch = ebase;

    const ulonglong2* sp2base = reinterpret_cast<const ulonglong2*>(s_sh + lrow * SROWF) + khalf * 64;

    // prefetch t=0 input (khalf0 only uses it)
    float2 inp_cur = make_float2(0.f, 0.f);
    if (khalf == 0) {
        if (PASS == 0) {
            int xv = x[0 * BB + grow];
            inp_cur = make_float2(g_table_t[(size_t)scol * VV + xv],
                                  g_table_t[(size_t)(HH + scol) * VV + xv]);
        } else {
            inp_cur = make_float2(__ldcg(&g_in1[0][scol * BB + grow]),
                                  __ldcg(&g_in1[0][(HH + scol) * BB + grow]));
        }
    }

    for (int t = 0; t < TT; ++t) {
        float2 inp_next = make_float2(0.f, 0.f);
        for (int d = 0; d < 4; ++d) {
            // ---- stage state tile [32][512] into padded smem ----
            if (t == 0 && d == 0) {
#pragma unroll
                for (int i = tid; i < 4096; i += NTH) {
                    int b = i >> 7, q = i & 127;
                    *reinterpret_cast<float4*>(s_sh + b * SROWF + 4 * q) =
                        make_float4(0.f, 0.f, 0.f, 0.f);
                }
            } else {
#pragma unroll
                for (int i = tid; i < 4096; i += NTH) {
                    int b = i >> 7, q = i & 127;
                    *reinterpret_cast<float4*>(s_sh + b * SROWF + 4 * q) =
                        __ldcg(reinterpret_cast<const float4*>(
                            s_cur + (size_t)(rg * 32 + b) * HH + 4 * q));
                }
            }
            __syncthreads();

            // prefetch next-t input during compute
            if (d == 0 && khalf == 0 && t + 1 < TT) {
                if (PASS == 0) {
                    int xv = x[(t + 1) * BB + grow];
                    inp_next = make_float2(g_table_t[(size_t)scol * VV + xv],
                                           g_table_t[(size_t)(HH + scol) * VV + xv]);
                } else {
                    inp_next = make_float2(__ldcg(&g_in1[t + 1][scol * BB + grow]),
                                           __ldcg(&g_in1[t + 1][(HH + scol) * BB + grow]));
                }
            }

            // ---- k-packed dot over this thread's 256 k's (64 float4 = 64 ull2)
            ull ah0 = pk2(0.f, 0.f), ag0 = pk2(0.f, 0.f);
            ull ah1 = pk2(0.f, 0.f), ag1 = pk2(0.f, 0.f);
            const ulonglong2* wp = w_pk + (size_t)(d * 8 + c) * WCOL + khalf * 128;
#pragma unroll 8
            for (int q = 0; q < 64; ++q) {
                ulonglong2 sv = sp2base[q];           // k 4q..4q+3 (packed pairs)
                ulonglong2 wA = wp[2 * q];            // kpair 2q  : (wh,wh),(wg,wg)
                ulonglong2 wB = wp[2 * q + 1];        // kpair 2q+1
                ah0 = fma2(sv.x, wA.x, ah0);
                ag0 = fma2(sv.x, wA.y, ag0);
                ah1 = fma2(sv.y, wB.x, ah1);
                ag1 = fma2(sv.y, wB.y, ag1);
            }
            float2 hp = upk2(add2(ah0, ah1));
            float2 gp = upk2(add2(ag0, ag1));
            float h_part = hp.x + hp.y;
            float g_part = gp.x + gp.y;

            if (khalf == 1) scratch[lrow * 8 + c] = make_float2(h_part, g_part);
            __syncthreads();

            if (khalf == 0) {
                float2 o = scratch[lrow * 8 + c];
                float acc_h = bh[d] + h_part + o.x;
                float acc_g = bg[d] + g_part + o.y;
                if (d == 0) { acc_h += inp_cur.x; acc_g += inp_cur.y; }

                float s_old = s_sh[lrow * SROWF + scol];
                float gt = 1.0f / (1.0f + expf(-acc_g));
                float ht = tanhf(acc_h);
                float s_new = ht * gt + s_old * (1.0f - gt);

                s_nxt[(size_t)grow * HH + scol] = s_new;
                if (d == 3) {
                    float* ob = (PASS == 0) ? g_out0[t] : g_out1[t];
                    ob[scol * BB + grow] = s_new;
                }
            }

            ++epoch;
            gbar(rg, cid, tid, epoch);

            const float* tmp = s_nxt;
            s_nxt = (float*)s_cur;
            s_cur = tmp;
        }
        inp_cur = inp_next;
    }
}

// ---------------------------------------------------------------------------
// g_in1[t][j][b] = sum_h g_out0[t][h][b] * w_in[1][h][j]   (FFMA2)
// ---------------------------------------------------------------------------
__global__ void k_inp1(const float* __restrict__ w_in) {
    int bid = blockIdx.x;
    int t   = bid >> 4;
    int jb  = bid & 15;
    int tid = threadIdx.x;
    int b   = tid & 63;
    int js  = tid >> 6;
    int j0  = jb * 64 + js * 16;

    ull acc[8];
#pragma unroll
    for (int i = 0; i < 8; ++i) acc[i] = pk2(0.f, 0.f);

    const float* o  = g_out0[t];
    const float* w1 = w_in + (size_t)EE * (2 * HH);
#pragma unroll 2
    for (int h = 0; h < HH; ++h) {
        ull svp = pkd(o[h * BB + b]);
        const ulonglong2* wr = reinterpret_cast<const ulonglong2*>(w1 + (size_t)h * (2 * HH) + j0);
        ulonglong2 q0 = wr[0], q1 = wr[1], q2 = wr[2], q3 = wr[3];
        acc[0] = fma2(svp, q0.x, acc[0]);  acc[1] = fma2(svp, q0.y, acc[1]);
        acc[2] = fma2(svp, q1.x, acc[2]);  acc[3] = fma2(svp, q1.y, acc[3]);
        acc[4] = fma2(svp, q2.x, acc[4]);  acc[5] = fma2(svp, q2.y, acc[5]);
        acc[6] = fma2(svp, q3.x, acc[6]);  acc[7] = fma2(svp, q3.y, acc[7]);
    }
#pragma unroll
    for (int i = 0; i < 8; ++i) {
        float2 v = upk2(acc[i]);
        g_in1[t][(j0 + 2 * i) * BB + b]     = v.x;
        g_in1[t][(j0 + 2 * i + 1) * BB + b] = v.y;
    }
}

// ---------------------------------------------------------------------------
__global__ void k_logits(const float* __restrict__ w_fc,
                         const float* __restrict__ b_fc,
                         float* __restrict__ out) {
    int bid = blockIdx.x;
    int t   = bid >> 2;
    int vb  = bid & 3;
    int tid = threadIdx.x;
    int b   = tid & 63;
    int vs  = tid >> 6;
    int v0  = vb * 64 + vs * 16;

    ull acc[8];
    const ulonglong2* bp = reinterpret_cast<const ulonglong2*>(b_fc + v0);
#pragma unroll
    for (int i = 0; i < 4; ++i) {
        ulonglong2 bq = bp[i];
        acc[2 * i] = bq.x; acc[2 * i + 1] = bq.y;
    }

    const float* o = g_out1[t];
#pragma unroll 2
    for (int h = 0; h < HH; ++h) {
        ull svp = pkd(o[h * BB + b]);
        const ulonglong2* wr = reinterpret_cast<const ulonglong2*>(w_fc + (size_t)h * VV + v0);
        ulonglong2 q0 = wr[0], q1 = wr[1], q2 = wr[2], q3 = wr[3];
        acc[0] = fma2(svp, q0.x, acc[0]);  acc[1] = fma2(svp, q0.y, acc[1]);
        acc[2] = fma2(svp, q1.x, acc[2]);  acc[3] = fma2(svp, q1.y, acc[3]);
        acc[4] = fma2(svp, q2.x, acc[4]);  acc[5] = fma2(svp, q2.y, acc[5]);
        acc[6] = fma2(svp, q3.x, acc[6]);  acc[7] = fma2(svp, q3.y, acc[7]);
    }

    ull* dst = reinterpret_cast<ull*>(out + ((size_t)(t * BB + b)) * VV + v0);
#pragma unroll
    for (int i = 0; i < 8; ++i) dst[i] = acc[i];
}

// ---------------------------------------------------------------------------
__global__ void k_sfinal(float* __restrict__ out, int l) {
    int idx = blockIdx.x * blockDim.x + threadIdx.x;
    if (idx >= BB * HH) return;
    out[(size_t)TT * BB * VV + (size_t)l * BB * HH + idx] = g_stateA[idx];
}

// ---------------------------------------------------------------------------
extern "C" void kernel_launch(void* const* d_in, const int* in_sizes, int n_in,
                              void* d_out, int out_size) {
    const int*   x    = (const int*)  d_in[0];
    const float* emb  = (const float*)d_in[1];
    const float* w_in = (const float*)d_in[2];
    const float* w_h  = (const float*)d_in[3];
    const float* b_h  = (const float*)d_in[4];
    const float* w_fc = (const float*)d_in[5];
    const float* b_fc = (const float*)d_in[6];
    float* out = (float*)d_out;

    const int smem_bytes = 131584 + 32 * SROWF * 4 + 2048;   // 200192 B
    static bool attr_done = false;
    if (!attr_done) {
        cudaFuncSetAttribute(k_rhn<0>, cudaFuncAttributeMaxDynamicSharedMemorySize, smem_bytes);
        cudaFuncSetAttribute(k_rhn<1>, cudaFuncAttributeMaxDynamicSharedMemorySize, smem_bytes);
        attr_done = true;
    }

    const bool has_sfinal = (out_size >= TT * BB * VV + 2 * BB * HH);

    k_reset<<<(GRID_REC * 32 + 255) / 256, 256>>>();                     // 1
    k_table<<<VV, 256>>>(emb, w_in);                                     // 2
    k_noop<<<1, 32>>>();                                                 // 3 (slot pad)
    k_rhn<0><<<GRID_REC, NTH, smem_bytes>>>(x, w_h, b_h, 0u);            // 4 <- profiled
    if (has_sfinal)
        k_sfinal<<<(BB * HH + 255) / 256, 256>>>(out, 0);
    k_inp1<<<TT * 16, 256>>>(w_in);
    k_rhn<1><<<GRID_REC, NTH, smem_bytes>>>(x, w_h, b_h, 2048u);
    k_logits<<<TT * 4, 256>>>(w_fc, b_fc, out);
    if (has_sfinal)
        k_sfinal<<<(BB * HH + 255) / 256, 256>>>(out, 1);
}

// round 7
// speedup vs baseline: 1.2436x; 1.1502x over previous
#include <cuda_runtime.h>
#include <math.h>

#define TT 512
#define BB 64
#define VV 256
#define EE 512
#define HH 512

#define GRID_REC 128
#define NTH 512

#define WCOL  257      // ull2 stride per (d,col) weight column (padded, conflict-free)

typedef unsigned long long ull;
__device__ __forceinline__ ull pk2(float x, float y) {
    ull r; asm("mov.b64 %0,{%1,%2};" : "=l"(r) : "f"(x), "f"(y)); return r;
}
__device__ __forceinline__ ull pkd(float x) {
    ull r; asm("mov.b64 %0,{%1,%1};" : "=l"(r) : "f"(x)); return r;
}
__device__ __forceinline__ ull fma2(ull a, ull b, ull c) {
    ull d; asm("fma.rn.f32x2 %0,%1,%2,%3;" : "=l"(d) : "l"(a), "l"(b), "l"(c)); return d;
}
__device__ __forceinline__ ull add2(ull a, ull b) {
    ull d; asm("add.rn.f32x2 %0,%1,%2;" : "=l"(d) : "l"(a), "l"(b)); return d;
}
__device__ __forceinline__ float2 upk2(ull a) {
    float2 r; asm("mov.b64 {%0,%1},%2;" : "=f"(r.x), "=f"(r.y) : "l"(a)); return r;
}

// ---------------------------------------------------------------------------
__device__ float g_table_t[2 * HH * VV];          // [j][v] : (emb @ w_in[0])^T
__device__ float g_stateA[BB * HH];               // state ping [b][k]
__device__ float g_stateB[BB * HH];               // state pong [b][k]
__device__ float g_out0[TT][HH * BB];             // layer-0 outputs [t][h][b]
__device__ float g_out1[TT][HH * BB];             // layer-1 outputs [t][h][b]
__device__ float g_in1[TT][2 * HH * BB];          // layer-1 input preact [t][j][b]
__device__ unsigned g_cnt[2 * 32];                // monotonic arrival counter per rowgroup

__global__ void k_reset() {
    int idx = blockIdx.x * blockDim.x + threadIdx.x;
    if (idx < 2 * 32) g_cnt[idx] = 0u;
}

__global__ void k_zero() {        // zero state ping buffer (pass entry condition)
    int idx = blockIdx.x * blockDim.x + threadIdx.x;
    if (idx < BB * HH) g_stateA[idx] = 0.0f;
}

// ---------------------------------------------------------------------------
__global__ void k_table(const float* __restrict__ emb,
                        const float* __restrict__ w_in) {
    int v = blockIdx.x;
    int j = threadIdx.x * 4;
    const float* er = emb + v * EE;
    float4 acc = make_float4(0.f, 0.f, 0.f, 0.f);
#pragma unroll 4
    for (int e = 0; e < EE; ++e) {
        float ev = er[e];
        float4 wv = *reinterpret_cast<const float4*>(w_in + (size_t)e * (2 * HH) + j);
        acc.x = fmaf(ev, wv.x, acc.x);
        acc.y = fmaf(ev, wv.y, acc.y);
        acc.z = fmaf(ev, wv.z, acc.z);
        acc.w = fmaf(ev, wv.w, acc.w);
    }
    g_table_t[(j + 0) * VV + v] = acc.x;
    g_table_t[(j + 1) * VV + v] = acc.y;
    g_table_t[(j + 2) * VV + v] = acc.z;
    g_table_t[(j + 3) * VV + v] = acc.w;
}

// ---------------------------------------------------------------------------
// sync primitives
// ---------------------------------------------------------------------------
__device__ __forceinline__ void arrive_rg(unsigned* cnt) {
    asm volatile("fence.proxy.async;" ::: "memory");
    asm volatile("membar.gl;" ::: "memory");
    asm volatile("red.release.gpu.global.add.u32 [%0], 1;" :: "l"(cnt) : "memory");
}
__device__ __forceinline__ void poll_rg(unsigned* cnt, unsigned target) {
    unsigned v;
    do {
        asm volatile("ld.acquire.gpu.global.u32 %0,[%1];" : "=r"(v) : "l"(cnt) : "memory");
    } while (v < target);
}
__device__ __forceinline__ void mbar_expect_tma(unsigned mbar, unsigned dst,
                                                const float* src, unsigned bytes) {
    asm volatile("mbarrier.arrive.expect_tx.shared.b64 _, [%0], %1;"
                 :: "r"(mbar), "r"(bytes) : "memory");
    asm volatile("cp.async.bulk.shared::cta.global.mbarrier::complete_tx::bytes [%0],[%1],%2,[%3];"
                 :: "r"(dst), "l"(src), "r"(bytes), "r"(mbar) : "memory");
}
__device__ __forceinline__ void mbar_wait(unsigned mbar, unsigned parity) {
    asm volatile(
        "{\n\t.reg .pred P;\n\t"
        "LW_%=:\n\t"
        "mbarrier.try_wait.parity.acquire.cta.shared::cta.b64 P,[%0],%1,0x989680;\n\t"
        "@P bra LD_%=;\n\t"
        "bra LW_%=;\n\t"
        "LD_%=:\n\t}"
        :: "r"(mbar), "r"(parity) : "memory");
}

// ---------------------------------------------------------------------------
// Persistent RHN pass. 128 CTAs = 2 rowgroup domains x 64 colgroups.
// CTA tile: 32 rows x 8 h-cols. 512 thr: warp = 4 rows x 8 cols, k split in 2.
// State tile staged per step via 1D bulk TMA (no L1tex wavefronts), read with
// per-row rotated k-order for bank-conflict-free access from the unpadded tile.
// Grid sync: red.add counter + poll by thread0; workers park on the TMA mbarrier.
// ---------------------------------------------------------------------------
template <int PASS>
__global__ void __launch_bounds__(NTH, 1) k_rhn(
    const int*   __restrict__ x,
    const float* __restrict__ w_h,
    const float* __restrict__ b_h)
{
    extern __shared__ float smraw[];
    ulonglong2* w_pk    = reinterpret_cast<ulonglong2*>(smraw);          // [4][8][WCOL] 131584 B
    float*      s_sh    = smraw + 32896;                                 // [32][512]     65536 B
    float2*     scratch = reinterpret_cast<float2*>(s_sh + 32 * 512);    // [32][8]        2048 B
    ull*        mbar    = reinterpret_cast<ull*>(scratch + 32 * 8);      //                   8 B

    const int tid   = threadIdx.x;
    const int cid   = blockIdx.x;
    const int rg    = cid & 1;
    const int cg    = cid >> 1;
    const int w     = tid >> 5;
    const int lane  = tid & 31;
    const int rr    = lane >> 3;        // row within quad (0..3)
    const int c     = lane & 7;
    const int wq    = w & 7;
    const int khalf = w >> 3;
    const int lrow  = wq * 4 + rr;
    const int grow  = rg * 32 + lrow;
    const int scol  = cg * 8 + c;

    unsigned smem_base;
    asm("{ .reg .u64 t; cvta.to.shared.u64 t, %1; cvt.u32.u64 %0, t; }"
        : "=r"(smem_base) : "l"(smraw));
    const unsigned mbar_a = smem_base + 32896 * 4 + 32 * 512 * 4 + 32 * 8 * 8;
    const unsigned ssh_a  = smem_base + 32896 * 4;

    if (tid == 0) {
        asm volatile("mbarrier.init.shared.b64 [%0], 1;" :: "r"(mbar_a) : "memory");
    }

    // ---- stage weights (h,g,k-pair packed, padded) ----
    for (int idx = tid; idx < 4 * 256 * 8; idx += NTH) {
        int cp = idx & 7;
        int kp = (idx >> 3) & 255;
        int d  = idx >> 11;
        const float* b0 = w_h + (((size_t)(PASS * 4 + d) * HH + 2 * kp) * (2 * HH)) + cg * 8 + cp;
        const float* b1 = b0 + 2 * HH;
        w_pk[(d * 8 + cp) * WCOL + kp] =
            make_ulonglong2(pk2(b0[0], b1[0]), pk2(b0[HH], b1[HH]));
    }

    float bh[4], bg[4];
#pragma unroll
    for (int d = 0; d < 4; ++d) {
        bh[d] = b_h[(size_t)(PASS * 4 + d) * (2 * HH) + scol];
        bg[d] = b_h[(size_t)(PASS * 4 + d) * (2 * HH) + HH + scol];
    }
    __syncthreads();

    const float* s_cur = g_stateA;
    float*       s_nxt = g_stateB;
    unsigned* cnt = (unsigned*)&g_cnt[rg * 32];
    const unsigned pbase = (PASS == 0) ? 0u : 2048u;

    const ulonglong2* s2   = reinterpret_cast<const ulonglong2*>(s_sh);
    const ulonglong2* wpB  = w_pk;
    const int rowbase = lrow * 128 + khalf * 64;   // float4 index of this thread's window
    const int rot     = 2 * rr;

    // prefetch t=0 input (khalf0 consumes it)
    float2 inp_cur = make_float2(0.f, 0.f);
    if (khalf == 0) {
        if (PASS == 0) {
            int xv = x[0 * BB + grow];
            inp_cur = make_float2(g_table_t[(size_t)scol * VV + xv],
                                  g_table_t[(size_t)(HH + scol) * VV + xv]);
        } else {
            inp_cur = make_float2(__ldcg(&g_in1[0][scol * BB + grow]),
                                  __ldcg(&g_in1[0][(HH + scol) * BB + grow]));
        }
    }

    unsigned sidx = 0;
    for (int t = 0; t < TT; ++t) {
        float2 inp_next = make_float2(0.f, 0.f);
        for (int d = 0; d < 4; ++d) {
            // ---- top: wait all CTAs' previous-step stores, then TMA-stage state
            if (tid == 0) {
                if (sidx > 0) poll_rg(cnt, 64u * (pbase + sidx));
                mbar_expect_tma(mbar_a, ssh_a, s_cur + (size_t)rg * 32 * HH, 32 * HH * 4);
            }
            mbar_wait(mbar_a, sidx & 1u);

            // prefetch next-t input during compute
            if (d == 0 && khalf == 0 && t + 1 < TT) {
                if (PASS == 0) {
                    int xv = x[(t + 1) * BB + grow];
                    inp_next = make_float2(g_table_t[(size_t)scol * VV + xv],
                                           g_table_t[(size_t)(HH + scol) * VV + xv]);
                } else {
                    inp_next = make_float2(__ldcg(&g_in1[t + 1][scol * BB + grow]),
                                           __ldcg(&g_in1[t + 1][(HH + scol) * BB + grow]));
                }
            }

            // ---- k-packed dot, rotated order (bank-conflict-free, reassoc only)
            ull ah0 = pk2(0.f, 0.f), ag0 = pk2(0.f, 0.f);
            ull ah1 = pk2(0.f, 0.f), ag1 = pk2(0.f, 0.f);
            const ulonglong2* wp = wpB + (size_t)(d * 8 + c) * WCOL + khalf * 128;
#pragma unroll 8
            for (int i = 0; i < 64; ++i) {
                int qq = (i + rot) & 63;
                ulonglong2 sv = s2[rowbase + qq];
                ulonglong2 wA = wp[2 * qq];
                ulonglong2 wB = wp[2 * qq + 1];
                ah0 = fma2(sv.x, wA.x, ah0);
                ag0 = fma2(sv.x, wA.y, ag0);
                ah1 = fma2(sv.y, wB.x, ah1);
                ag1 = fma2(sv.y, wB.y, ag1);
            }
            float2 hp = upk2(add2(ah0, ah1));
            float2 gp = upk2(add2(ag0, ag1));
            float h_part = hp.x + hp.y;
            float g_part = gp.x + gp.y;

            if (khalf == 1) scratch[lrow * 8 + c] = make_float2(h_part, g_part);
            __syncthreads();

            if (khalf == 0) {
                float2 o = scratch[lrow * 8 + c];
                float acc_h = bh[d] + h_part + o.x;
                float acc_g = bg[d] + g_part + o.y;
                if (d == 0) { acc_h += inp_cur.x; acc_g += inp_cur.y; }

                float s_old = s_sh[lrow * 512 + scol];
                float gt = 1.0f / (1.0f + expf(-acc_g));
                float ht = tanhf(acc_h);
                float s_new = ht * gt + s_old * (1.0f - gt);

                s_nxt[(size_t)grow * HH + scol] = s_new;
                if (d == 3) {
                    float* ob = (PASS == 0) ? g_out0[t] : g_out1[t];
                    ob[scol * BB + grow] = s_new;
                }
            }

            __syncthreads();                 // all STGs issued before arrive
            if (tid == 0) arrive_rg(cnt);

            const float* tmp = s_nxt;
            s_nxt = (float*)s_cur;
            s_cur = tmp;
            ++sidx;
        }
        inp_cur = inp_next;
    }
}

// ---------------------------------------------------------------------------
// g_in1[t][j][b] = sum_h g_out0[t][h][b] * w_in[1][h][j]   (FFMA2)
// ---------------------------------------------------------------------------
__global__ void k_inp1(const float* __restrict__ w_in) {
    int bid = blockIdx.x;
    int t   = bid >> 4;
    int jb  = bid & 15;
    int tid = threadIdx.x;
    int b   = tid & 63;
    int js  = tid >> 6;
    int j0  = jb * 64 + js * 16;

    ull acc[8];
#pragma unroll
    for (int i = 0; i < 8; ++i) acc[i] = pk2(0.f, 0.f);

    const float* o  = g_out0[t];
    const float* w1 = w_in + (size_t)EE * (2 * HH);
#pragma unroll 2
    for (int h = 0; h < HH; ++h) {
        ull svp = pkd(o[h * BB + b]);
        const ulonglong2* wr = reinterpret_cast<const ulonglong2*>(w1 + (size_t)h * (2 * HH) + j0);
        ulonglong2 q0 = wr[0], q1 = wr[1], q2 = wr[2], q3 = wr[3];
        acc[0] = fma2(svp, q0.x, acc[0]);  acc[1] = fma2(svp, q0.y, acc[1]);
        acc[2] = fma2(svp, q1.x, acc[2]);  acc[3] = fma2(svp, q1.y, acc[3]);
        acc[4] = fma2(svp, q2.x, acc[4]);  acc[5] = fma2(svp, q2.y, acc[5]);
        acc[6] = fma2(svp, q3.x, acc[6]);  acc[7] = fma2(svp, q3.y, acc[7]);
    }
#pragma unroll
    for (int i = 0; i < 8; ++i) {
        float2 v = upk2(acc[i]);
        g_in1[t][(j0 + 2 * i) * BB + b]     = v.x;
        g_in1[t][(j0 + 2 * i + 1) * BB + b] = v.y;
    }
}

// ---------------------------------------------------------------------------
__global__ void k_logits(const float* __restrict__ w_fc,
                         const float* __restrict__ b_fc,
                         float* __restrict__ out) {
    int bid = blockIdx.x;
    int t   = bid >> 2;
    int vb  = bid & 3;
    int tid = threadIdx.x;
    int b   = tid & 63;
    int vs  = tid >> 6;
    int v0  = vb * 64 + vs * 16;

    ull acc[8];
    const ulonglong2* bp = reinterpret_cast<const ulonglong2*>(b_fc + v0);
#pragma unroll
    for (int i = 0; i < 4; ++i) {
        ulonglong2 bq = bp[i];
        acc[2 * i] = bq.x; acc[2 * i + 1] = bq.y;
    }

    const float* o = g_out1[t];
#pragma unroll 2
    for (int h = 0; h < HH; ++h) {
        ull svp = pkd(o[h * BB + b]);
        const ulonglong2* wr = reinterpret_cast<const ulonglong2*>(w_fc + (size_t)h * VV + v0);
        ulonglong2 q0 = wr[0], q1 = wr[1], q2 = wr[2], q3 = wr[3];
        acc[0] = fma2(svp, q0.x, acc[0]);  acc[1] = fma2(svp, q0.y, acc[1]);
        acc[2] = fma2(svp, q1.x, acc[2]);  acc[3] = fma2(svp, q1.y, acc[3]);
        acc[4] = fma2(svp, q2.x, acc[4]);  acc[5] = fma2(svp, q2.y, acc[5]);
        acc[6] = fma2(svp, q3.x, acc[6]);  acc[7] = fma2(svp, q3.y, acc[7]);
    }

    ull* dst = reinterpret_cast<ull*>(out + ((size_t)(t * BB + b)) * VV + v0);
#pragma unroll
    for (int i = 0; i < 8; ++i) dst[i] = acc[i];
}

// ---------------------------------------------------------------------------
__global__ void k_sfinal(float* __restrict__ out, int l) {
    int idx = blockIdx.x * blockDim.x + threadIdx.x;
    if (idx >= BB * HH) return;
    out[(size_t)TT * BB * VV + (size_t)l * BB * HH + idx] = g_stateA[idx];
}

// ---------------------------------------------------------------------------
extern "C" void kernel_launch(void* const* d_in, const int* in_sizes, int n_in,
                              void* d_out, int out_size) {
    const int*   x    = (const int*)  d_in[0];
    const float* emb  = (const float*)d_in[1];
    const float* w_in = (const float*)d_in[2];
    const float* w_h  = (const float*)d_in[3];
    const float* b_h  = (const float*)d_in[4];
    const float* w_fc = (const float*)d_in[5];
    const float* b_fc = (const float*)d_in[6];
    float* out = (float*)d_out;

    // 131584 (weights) + 65536 (state) + 2048 (scratch) + 16 (mbar) = 199184 B
    const int smem_bytes = 131584 + 65536 + 2048 + 16;
    static bool attr_done = false;
    if (!attr_done) {
        cudaFuncSetAttribute(k_rhn<0>, cudaFuncAttributeMaxDynamicSharedMemorySize, smem_bytes);
        cudaFuncSetAttribute(k_rhn<1>, cudaFuncAttributeMaxDynamicSharedMemorySize, smem_bytes);
        attr_done = true;
    }

    const bool has_sfinal = (out_size >= TT * BB * VV + 2 * BB * HH);

    k_reset<<<1, 64>>>();                                               // 1
    k_table<<<VV, 256>>>(emb, w_in);                                    // 2
    k_zero<<<(BB * HH + 255) / 256, 256>>>();                           // 3
    k_rhn<0><<<GRID_REC, NTH, smem_bytes>>>(x, w_h, b_h);               // 4 <- profiled
    if (has_sfinal)
        k_sfinal<<<(BB * HH + 255) / 256, 256>>>(out, 0);
    k_inp1<<<TT * 16, 256>>>(w_in);
    k_zero<<<(BB * HH + 255) / 256, 256>>>();
    k_rhn<1><<<GRID_REC, NTH, smem_bytes>>>(x, w_h, b_h);
    k_logits<<<TT * 4, 256>>>(w_fc, b_fc, out);
    if (has_sfinal)
        k_sfinal<<<(BB * HH + 255) / 256, 256>>>(out, 1);
}